// round 10
// baseline (speedup 1.0000x reference)
#include <cuda_runtime.h>
#include <cstdint>

#define HH 64
#define WW 64
#define HW 4096
#define CCH 256
#define NK 33

// Scratch
__device__ float g_GT[2u * 4096u * 256u];  // G transposed: [b][p][c]
__device__ float g_M2[256u * 256u];        // M2[c][d] = sum_o Wg[o,c] Wf[o,d]
__device__ float g_u[256u];                // u[d]     = sum_o bg[o]   Wf[o,d]
__device__ unsigned g_gate = 0u;
__device__ unsigned g_done = 0u;

// ---------------------------------------------------------------------------
// f32x2 packed helpers (FFMA2 via PTX fma.rn.f32x2)
// ---------------------------------------------------------------------------
__device__ __forceinline__ unsigned long long pack2_bcast(float x) {
  unsigned long long r;
  asm("mov.b64 %0, {%1, %1};" : "=l"(r) : "f"(x));
  return r;
}
__device__ __forceinline__ unsigned long long ffma2(unsigned long long a,
                                                    unsigned long long b,
                                                    unsigned long long c) {
  unsigned long long d;
  asm("fma.rn.f32x2 %0, %1, %2, %3;" : "=l"(d) : "l"(a), "l"(b), "l"(c));
  return d;
}
__device__ __forceinline__ void unpack2(unsigned long long v, float& lo, float& hi) {
  asm("mov.b64 {%0, %1}, %2;" : "=f"(lo), "=f"(hi) : "l"(v));
}

// ---------------------------------------------------------------------------
// Kernel 1 (fused): prep (M2, u) + GT = Xt @ M2 (+u), GT[p][d]. (R9, unchanged)
// ---------------------------------------------------------------------------
#define PSTR 36
#define FUSED_SMEM (2 * 256 * PSTR * (int)sizeof(float))  // 73728 B

__global__ __launch_bounds__(256) void psla_gemm_fused(
    const float* __restrict__ Fte, const float* __restrict__ Wf,
    const float* __restrict__ Wg, const float* __restrict__ bg) {
  extern __shared__ float dsm[];
  const int bid = blockIdx.x;
  const int tid = threadIdx.x;

  if (bid < 64) {
    float (*sg)[PSTR] = (float (*)[PSTR])dsm;
    float (*sf)[PSTR] = (float (*)[PSTR])(dsm + 256 * PSTR);
    const int c0 = (bid & 7) * 32;
    const int d0 = (bid >> 3) * 32;

    float4 ga[8], fa[8];
#pragma unroll
    for (int j = 0; j < 8; j++) {
      ga[j] = *(const float4*)(Wg + (size_t)tid * 256 + c0 + 4 * j);
      fa[j] = *(const float4*)(Wf + (size_t)tid * 256 + d0 + 4 * j);
    }
#pragma unroll
    for (int j = 0; j < 8; j++) {
      *(float4*)&sg[tid][4 * j] = ga[j];
      *(float4*)&sf[tid][4 * j] = fa[j];
    }
    __syncthreads();

    const int tc = (tid & 15) * 2, td = (tid >> 4) * 2;
    float a00 = 0.f, a01 = 0.f, a10 = 0.f, a11 = 0.f;
#pragma unroll 8
    for (int kk = 0; kk < 256; kk++) {
      const float2 g2 = *(const float2*)&sg[kk][tc];
      const float2 f2 = *(const float2*)&sf[kk][td];
      a00 = fmaf(f2.x, g2.x, a00);
      a01 = fmaf(f2.x, g2.y, a01);
      a10 = fmaf(f2.y, g2.x, a10);
      a11 = fmaf(f2.y, g2.y, a11);
    }
    g_M2[(size_t)(c0 + tc + 0) * 256 + d0 + td + 0] = a00;
    g_M2[(size_t)(c0 + tc + 1) * 256 + d0 + td + 0] = a01;
    g_M2[(size_t)(c0 + tc + 0) * 256 + d0 + td + 1] = a10;
    g_M2[(size_t)(c0 + tc + 1) * 256 + d0 + td + 1] = a11;

    __threadfence();
    __syncthreads();
    if (tid == 0) atomicAdd(&g_gate, 1u);
  } else if (bid == 64) {
    float s0 = 0.f, s1 = 0.f, s2 = 0.f, s3 = 0.f;
#pragma unroll
    for (int o = 0; o < 256; o += 4) {
      s0 = fmaf(bg[o + 0], Wf[(o + 0) * 256 + tid], s0);
      s1 = fmaf(bg[o + 1], Wf[(o + 1) * 256 + tid], s1);
      s2 = fmaf(bg[o + 2], Wf[(o + 2) * 256 + tid], s2);
      s3 = fmaf(bg[o + 3], Wf[(o + 3) * 256 + tid], s3);
    }
    g_u[tid] = (s0 + s1) + (s2 + s3);
    __threadfence();
    __syncthreads();
    if (tid == 0) atomicAdd(&g_gate, 1u);
  }

  if (tid == 0) {
    while (atomicAdd(&g_gate, 0u) < 65u) __nanosleep(64);
  }
  __syncthreads();

  {
    float* sA = dsm;
    float* sB = dsm + 2 * 8 * 132;

    const int yy = bid >> 5;
    const int b = yy & 1;
    const int o0 = (yy >> 1) * 128;
    const int p0 = (bid & 31) * 128;
    const float* X = Fte + (size_t)b * CCH * HW;
    float* Go = g_GT + (size_t)b * HW * CCH;

    const int tx = tid & 15, ty = tid >> 4;
    const int row = tid >> 5, col = (tid & 31) * 4;

    unsigned long long acc2[8][4];
#pragma unroll
    for (int i = 0; i < 8; i++)
#pragma unroll
      for (int j = 0; j < 4; j++) acc2[i][j] = 0ull;

    float4 av = *(const float4*)(X + (size_t)row * HW + p0 + col);
    float4 bv = *(const float4*)(g_M2 + (size_t)row * 256 + o0 + col);
    *(float4*)&sA[row * 132 + col] = av;
    *(float4*)&sB[row * 132 + col] = bv;
    __syncthreads();

    for (int t = 0; t < 32; t++) {
      if (t < 31) {
        const int k0 = (t + 1) * 8;
        av = *(const float4*)(X + (size_t)(k0 + row) * HW + p0 + col);
        bv = *(const float4*)(g_M2 + (size_t)(k0 + row) * 256 + o0 + col);
      }
      const float* cA = sA + (t & 1) * 8 * 132;
      const float* cB = sB + (t & 1) * 8 * 132;
#pragma unroll
      for (int kk = 0; kk < 8; kk++) {
        float a[8];
        *(float4*)&a[0] = *(const float4*)&cA[kk * 132 + ty * 8];
        *(float4*)&a[4] = *(const float4*)&cA[kk * 132 + ty * 8 + 4];
        unsigned long long b2[4];
        ulonglong2 bl0 = *(const ulonglong2*)&cB[kk * 132 + tx * 8];
        ulonglong2 bl1 = *(const ulonglong2*)&cB[kk * 132 + tx * 8 + 4];
        b2[0] = bl0.x; b2[1] = bl0.y; b2[2] = bl1.x; b2[3] = bl1.y;
        unsigned long long a2[8];
#pragma unroll
        for (int i = 0; i < 8; i++) a2[i] = pack2_bcast(a[i]);
#pragma unroll
        for (int i = 0; i < 8; i++)
#pragma unroll
          for (int j = 0; j < 4; j++)
            acc2[i][j] = ffma2(a2[i], b2[j], acc2[i][j]);
      }
      if (t < 31) {
        float* nA = sA + ((t & 1) ^ 1) * 8 * 132;
        float* nB = sB + ((t & 1) ^ 1) * 8 * 132;
        *(float4*)&nA[row * 132 + col] = av;
        *(float4*)&nB[row * 132 + col] = bv;
      }
      __syncthreads();
    }

    float4 u0 = *(const float4*)(g_u + o0 + tx * 8);
    float4 u1 = *(const float4*)(g_u + o0 + tx * 8 + 4);
#pragma unroll
    for (int i = 0; i < 8; i++) {
      const int p = p0 + ty * 8 + i;
      float r[8];
#pragma unroll
      for (int j = 0; j < 4; j++) unpack2(acc2[i][j], r[2 * j], r[2 * j + 1]);
      float4 v0, v1;
      v0.x = r[0] + u0.x; v0.y = r[1] + u0.y;
      v0.z = r[2] + u0.z; v0.w = r[3] + u0.w;
      v1.x = r[4] + u1.x; v1.y = r[5] + u1.y;
      v1.z = r[6] + u1.z; v1.w = r[7] + u1.w;
      *(float4*)(Go + (size_t)p * 256 + o0 + tx * 8) = v0;
      *(float4*)(Go + (size_t)p * 256 + o0 + tx * 8 + 4) = v1;
    }
  }

  __syncthreads();
  if (tid == 0) {
    const unsigned d = atomicAdd(&g_done, 1u);
    if (d == 127u) {
      atomicExch(&g_gate, 0u);
      atomicExch(&g_done, 0u);
    }
  }
}

// ---------------------------------------------------------------------------
// Kernel 2: sparse local attention, v7 — RESIDENT HALO.
// Tile = 8(x) x 4(y) px, halo 16x12 = 192 sites, ALL 256 channels in smem:
//   smem [8 chunks][192 sites][36] = 221184 B.  ONE __syncthreads total.
// 256 threads = 32 px * 8 subs of 4 ch. Fill: threads 0..191 own one site,
// stage channel-strided LDG through registers (coalesced; STS 9q+j pattern).
// Phase A/B: LDS.128 at 9s+sub — conflict-free. grid = 8 x 16 x 2 = 256.
// ---------------------------------------------------------------------------
#define SST 36
#define NSITE 192
#define CHSTR (NSITE * SST)  // 6912 floats per chunk
#define ATTN_SMEM (8 * CHSTR * (int)sizeof(float))  // 221184 B

__global__ __launch_bounds__(256) void psla_attn(const float* __restrict__ Ft,
                                                 float* __restrict__ out) {
  extern __shared__ float sm[];
  constexpr int kdx[NK] = {0, -1,-1,-1,0,0,1,1,1, -2,-2,-2,0,0,2,2,2,
                           -3,-3,-3,0,0,3,3,3, -4,-4,-4,0,0,4,4,4};
  constexpr int kdy[NK] = {0, -1,0,1,-1,1,-1,0,1, -2,0,2,-2,2,-2,0,2,
                           -3,0,3,-3,3,-3,0,3, -4,0,4,-4,4,-4,0,4};

  const int b = blockIdx.z;
  const int gx0 = blockIdx.x * 8, gy0 = blockIdx.y * 4;
  const int tid = threadIdx.x;
  const int px = tid >> 3, sub = tid & 7;
  const int lx = px & 7, ly = px >> 3;  // ly in 0..3
  const int gx = gx0 + lx, gy = gy0 + ly;
  const int gp = gy * WW + gx;

  const float* GTp = g_GT + ((size_t)b * HW + gp) * 256 + sub * 4;
  const float* Ftb = Ft + (size_t)b * CCH * HW;

  // ==== Fill: threads 0..191 own halo site q; all 8 chunks, one sync ====
  if (tid < NSITE) {
    const int q = tid;
    const int hy = gy0 - 4 + (q >> 4);   // rows 0..11 of 16-wide halo
    const int hx = gx0 - 4 + (q & 15);
    const bool hin = ((unsigned)hy < HH) && ((unsigned)hx < WW);
    const int haddr = hy * WW + hx;
    float* const myq = sm + q * SST;
#pragma unroll
    for (int chunk = 0; chunk < 8; chunk++) {
      float4 hv[8];
#pragma unroll
      for (int j = 0; j < 8; j++) {
        const int c = chunk * 32 + j * 4;
        float4 v;
        v.x = hin ? Ftb[(size_t)(c + 0) * HW + haddr] : 0.f;
        v.y = hin ? Ftb[(size_t)(c + 1) * HW + haddr] : 0.f;
        v.z = hin ? Ftb[(size_t)(c + 2) * HW + haddr] : 0.f;
        v.w = hin ? Ftb[(size_t)(c + 3) * HW + haddr] : 0.f;
        hv[j] = v;
      }
#pragma unroll
      for (int j = 0; j < 8; j++)
        *(float4*)(myq + chunk * CHSTR + j * 4) = hv[j];
    }
  }

  // eg: this thread's 4 channels per chunk (coalesced from GT[p][c]).
  float4 eg[8];
#pragma unroll
  for (int chunk = 0; chunk < 8; chunk++)
    eg[chunk] = *(const float4*)(GTp + chunk * 32);

  // Validity bitmask.
  unsigned long long vmask = 0ull;
#pragma unroll
  for (int k = 0; k < NK; k++)
    if ((unsigned)(gy + kdx[k]) < HH && (unsigned)(gx + kdy[k]) < WW)
      vmask |= (1ull << k);

  __syncthreads();  // the ONLY block-wide barrier

  // Center site base for this thread (site stride SST, sub offset).
  const float* const cbase =
      sm + ((ly + 4) * 16 + (lx + 4)) * SST + sub * 4;

  // ==== Phase A: aff[k] = <G(p), Ft(p+delta_k)> over all 8 chunks ====
  float aff[NK];
#pragma unroll
  for (int k = 0; k < NK; k++) aff[k] = 0.f;

#pragma unroll
  for (int chunk = 0; chunk < 8; chunk++) {
    const float* bp = cbase + chunk * CHSTR;
    const float4 e = eg[chunk];
#pragma unroll
    for (int k = 0; k < NK; k++) {
      const float4 v = *(const float4*)(bp + (kdx[k] * 16 + kdy[k]) * SST);
      float s = fmaf(e.x, v.x, 0.f);
      s = fmaf(e.y, v.y, s);
      s = fmaf(e.z, v.z, s);
      s = fmaf(e.w, v.w, s);
      aff[k] += s;
    }
  }

  // Reduce across the 8 channel-subgroups (in-warp: lanes xor 1,2,4).
#pragma unroll
  for (int k = 0; k < NK; k++) {
    aff[k] += __shfl_xor_sync(0xffffffffu, aff[k], 1);
    aff[k] += __shfl_xor_sync(0xffffffffu, aff[k], 2);
    aff[k] += __shfl_xor_sync(0xffffffffu, aff[k], 4);
  }

  // ==== Softmax over valid offsets ====
  float m = aff[0];
#pragma unroll
  for (int k = 1; k < NK; k++)
    if ((vmask >> k) & 1ull) m = fmaxf(m, aff[k]);
  float ssum = 0.f;
#pragma unroll
  for (int k = 0; k < NK; k++) {
    if ((vmask >> k) & 1ull) {
      aff[k] = __expf(aff[k] - m);
      ssum += aff[k];
    } else {
      aff[k] = 0.f;
    }
  }
  const float inv = 1.f / ssum;
#pragma unroll
  for (int k = 0; k < NK; k++) aff[k] *= inv;

  // ==== Phase B: out = sum_k w_k * Ft(p+delta_k); smem is read-only ====
#pragma unroll
  for (int chunk = 0; chunk < 8; chunk++) {
    const float* bp = cbase + chunk * CHSTR;
    unsigned long long a01 = 0ull, a23 = 0ull;
#pragma unroll
    for (int k = 0; k < NK; k++) {
      const ulonglong2 vv =
          *(const ulonglong2*)(bp + (kdx[k] * 16 + kdy[k]) * SST);
      const unsigned long long wk2 = pack2_bcast(aff[k]);
      a01 = ffma2(wk2, vv.x, a01);
      a23 = ffma2(wk2, vv.y, a23);
    }
    float o0, o1, o2, o3;
    unpack2(a01, o0, o1);
    unpack2(a23, o2, o3);
    float* op = out + (size_t)(b * CCH + chunk * 32 + sub * 4) * HW + gp;
    op[0] = o0;
    op[HW] = o1;
    op[2 * HW] = o2;
    op[3 * HW] = o3;
  }
}

// ---------------------------------------------------------------------------
extern "C" void kernel_launch(void* const* d_in, const int* in_sizes, int n_in,
                              void* d_out, int out_size) {
  const float* Ft  = (const float*)d_in[0];
  const float* Fte = (const float*)d_in[1];
  const float* Wf  = (const float*)d_in[2];
  // d_in[3] = bf: cancels in the softmax (constant in k) — unused.
  const float* Wg  = (const float*)d_in[4];
  const float* bg  = (const float*)d_in[5];
  float* out = (float*)d_out;

  cudaFuncSetAttribute(psla_gemm_fused,
                       cudaFuncAttributeMaxDynamicSharedMemorySize, FUSED_SMEM);
  cudaFuncSetAttribute(psla_attn, cudaFuncAttributeMaxDynamicSharedMemorySize,
                       ATTN_SMEM);

  psla_gemm_fused<<<128, 256, FUSED_SMEM>>>(Fte, Wf, Wg, bg);

  dim3 ga(8, 16, 2);  // W/8, H/4, B
  psla_attn<<<ga, 256, ATTN_SMEM>>>(Ft, out);
}

// round 11
// speedup vs baseline: 6.2932x; 6.2932x over previous
#include <cuda_runtime.h>
#include <cstdint>

#define HH 64
#define WW 64
#define HW 4096
#define CCH 256
#define NK 33

// Scratch
__device__ float g_G[2u * 256u * 4096u];  // G[b][d][p] = Mt @ Fte + u
__device__ float g_M[256u * 256u];        // Mt[d][c] = sum_o Wg[o,c] Wf[o,d]
__device__ float g_u[256u];               // u[d]     = sum_o bg[o]   Wf[o,d]
__device__ unsigned g_gate = 0u;
__device__ unsigned g_done = 0u;

// ---------------------------------------------------------------------------
// f32x2 packed helpers (FFMA2 via PTX fma.rn.f32x2)
// ---------------------------------------------------------------------------
__device__ __forceinline__ unsigned long long pack2_bcast(float x) {
  unsigned long long r;
  asm("mov.b64 %0, {%1, %1};" : "=l"(r) : "f"(x));
  return r;
}
__device__ __forceinline__ unsigned long long ffma2(unsigned long long a,
                                                    unsigned long long b,
                                                    unsigned long long c) {
  unsigned long long d;
  asm("fma.rn.f32x2 %0, %1, %2, %3;" : "=l"(d) : "l"(a), "l"(b), "l"(c));
  return d;
}
__device__ __forceinline__ void unpack2(unsigned long long v, float& lo, float& hi) {
  asm("mov.b64 {%0, %1}, %2;" : "=f"(lo), "=f"(hi) : "l"(v));
}

// ---------------------------------------------------------------------------
// Kernel 1 (fused): prep (Mt, u) + G = Mt @ Fte + u.  (R8 verbatim, 43 us)
// grid = 128 CTAs, one wave, spin-gate between phases.
// ---------------------------------------------------------------------------
#define PSTR 36
#define FUSED_SMEM (2 * 256 * PSTR * (int)sizeof(float))  // 73728 B

__global__ __launch_bounds__(256) void psla_gemm_fused(
    const float* __restrict__ Fte, const float* __restrict__ Wf,
    const float* __restrict__ Wg, const float* __restrict__ bg) {
  extern __shared__ float dsm[];
  const int bid = blockIdx.x;
  const int tid = threadIdx.x;

  if (bid < 64) {
    float (*sg)[PSTR] = (float (*)[PSTR])dsm;
    float (*sf)[PSTR] = (float (*)[PSTR])(dsm + 256 * PSTR);
    const int c0 = (bid & 7) * 32;
    const int d0 = (bid >> 3) * 32;

    float4 ga[8], fa[8];
#pragma unroll
    for (int j = 0; j < 8; j++) {
      ga[j] = *(const float4*)(Wg + (size_t)tid * 256 + c0 + 4 * j);
      fa[j] = *(const float4*)(Wf + (size_t)tid * 256 + d0 + 4 * j);
    }
#pragma unroll
    for (int j = 0; j < 8; j++) {
      *(float4*)&sg[tid][4 * j] = ga[j];
      *(float4*)&sf[tid][4 * j] = fa[j];
    }
    __syncthreads();

    const int tc = (tid & 15) * 2, td = (tid >> 4) * 2;
    float a00 = 0.f, a01 = 0.f, a10 = 0.f, a11 = 0.f;
#pragma unroll 8
    for (int kk = 0; kk < 256; kk++) {
      const float2 g2 = *(const float2*)&sg[kk][tc];
      const float2 f2 = *(const float2*)&sf[kk][td];
      a00 = fmaf(f2.x, g2.x, a00);
      a01 = fmaf(f2.x, g2.y, a01);
      a10 = fmaf(f2.y, g2.x, a10);
      a11 = fmaf(f2.y, g2.y, a11);
    }
    // Mt[d][c]
    g_M[(size_t)(d0 + td + 0) * 256 + c0 + tc + 0] = a00;
    g_M[(size_t)(d0 + td + 0) * 256 + c0 + tc + 1] = a01;
    g_M[(size_t)(d0 + td + 1) * 256 + c0 + tc + 0] = a10;
    g_M[(size_t)(d0 + td + 1) * 256 + c0 + tc + 1] = a11;

    __threadfence();
    __syncthreads();
    if (tid == 0) atomicAdd(&g_gate, 1u);
  } else if (bid == 64) {
    float s0 = 0.f, s1 = 0.f, s2 = 0.f, s3 = 0.f;
#pragma unroll
    for (int o = 0; o < 256; o += 4) {
      s0 = fmaf(bg[o + 0], Wf[(o + 0) * 256 + tid], s0);
      s1 = fmaf(bg[o + 1], Wf[(o + 1) * 256 + tid], s1);
      s2 = fmaf(bg[o + 2], Wf[(o + 2) * 256 + tid], s2);
      s3 = fmaf(bg[o + 3], Wf[(o + 3) * 256 + tid], s3);
    }
    g_u[tid] = (s0 + s1) + (s2 + s3);
    __threadfence();
    __syncthreads();
    if (tid == 0) atomicAdd(&g_gate, 1u);
  }

  if (tid == 0) {
    while (atomicAdd(&g_gate, 0u) < 65u) __nanosleep(64);
  }
  __syncthreads();

  {
    float* sA = dsm;            // [8][132]
    float* sB = dsm + 8 * 132;  // [8][132]

    const int yy = bid >> 5;
    const int b = yy & 1;
    const int o0 = (yy >> 1) * 128;
    const int p0 = (bid & 31) * 128;
    const float* X = Fte + (size_t)b * CCH * HW;
    float* Go = g_G + (size_t)b * CCH * HW;

    const int tx = tid & 15, ty = tid >> 4;

    unsigned long long acc2[8][4];
#pragma unroll
    for (int i = 0; i < 8; i++)
#pragma unroll
      for (int j = 0; j < 4; j++) acc2[i][j] = 0ull;

    const int arow = tid >> 1, acg = (tid & 1) * 4;
    const int brow = tid >> 5, bcol = (tid & 31) * 4;

    for (int k0 = 0; k0 < CCH; k0 += 8) {
      float4 av = *(const float4*)(g_M + (size_t)(o0 + arow) * CCH + k0 + acg);
      float4 bv = *(const float4*)(X + (size_t)(k0 + brow) * HW + p0 + bcol);
      __syncthreads();
      sA[(acg + 0) * 132 + arow] = av.x;
      sA[(acg + 1) * 132 + arow] = av.y;
      sA[(acg + 2) * 132 + arow] = av.z;
      sA[(acg + 3) * 132 + arow] = av.w;
      *(float4*)&sB[brow * 132 + bcol] = bv;
      __syncthreads();
#pragma unroll
      for (int kk = 0; kk < 8; kk++) {
        float a[8];
        *(float4*)&a[0] = *(const float4*)&sA[kk * 132 + ty * 8];
        *(float4*)&a[4] = *(const float4*)&sA[kk * 132 + ty * 8 + 4];
        unsigned long long b2[4];
        ulonglong2 bl0 = *(const ulonglong2*)&sB[kk * 132 + tx * 8];
        ulonglong2 bl1 = *(const ulonglong2*)&sB[kk * 132 + tx * 8 + 4];
        b2[0] = bl0.x; b2[1] = bl0.y; b2[2] = bl1.x; b2[3] = bl1.y;
        unsigned long long a2[8];
#pragma unroll
        for (int i = 0; i < 8; i++) a2[i] = pack2_bcast(a[i]);
#pragma unroll
        for (int i = 0; i < 8; i++)
#pragma unroll
          for (int j = 0; j < 4; j++)
            acc2[i][j] = ffma2(a2[i], b2[j], acc2[i][j]);
      }
    }

#pragma unroll
    for (int i = 0; i < 8; i++) {
      const int o = o0 + ty * 8 + i;
      const float bvv = g_u[o];
      float r[8];
#pragma unroll
      for (int j = 0; j < 4; j++) unpack2(acc2[i][j], r[2 * j], r[2 * j + 1]);
#pragma unroll
      for (int j = 0; j < 8; j += 4) {
        float4 v;
        v.x = r[j + 0] + bvv;
        v.y = r[j + 1] + bvv;
        v.z = r[j + 2] + bvv;
        v.w = r[j + 3] + bvv;
        *(float4*)(Go + (size_t)o * HW + p0 + tx * 8 + j) = v;
      }
    }
  }

  __syncthreads();
  if (tid == 0) {
    const unsigned d = atomicAdd(&g_done, 1u);
    if (d == 127u) {
      atomicExch(&g_gate, 0u);
      atomicExch(&g_done, 0u);
    }
  }
}

// ---------------------------------------------------------------------------
// Kernel 2: sparse local attention, v8 = R8 structure with 64-channel chunks.
// 8x8 px tile, 512 threads = 64 px * 8 subs; each sub handles 8 channels per
// 64-chunk (two float4 groups at +0 and +32). Double-buffered smem
// [2][256 sites][68] = 139264 B. 4 chunks per phase -> 10 barriers total.
// ---------------------------------------------------------------------------
#define SST 68
#define ABUF (256 * SST)  // 17408 floats per buffer

// Thread (q, h) loads channel groups g = h + 2j (j=0..7) of a 64-ch chunk.
__device__ __forceinline__ void fetch64(const float* __restrict__ P, int base,
                                        int h, bool hin, int haddr,
                                        float4* hv) {
#pragma unroll
  for (int j = 0; j < 8; j++) {
    const int c = base + (h + 2 * j) * 4;
    float4 v;
    v.x = hin ? P[(size_t)(c + 0) * HW + haddr] : 0.f;
    v.y = hin ? P[(size_t)(c + 1) * HW + haddr] : 0.f;
    v.z = hin ? P[(size_t)(c + 2) * HW + haddr] : 0.f;
    v.w = hin ? P[(size_t)(c + 3) * HW + haddr] : 0.f;
    hv[j] = v;
  }
}
__device__ __forceinline__ void store64(float* bufq, int h, const float4* hv) {
#pragma unroll
  for (int j = 0; j < 8; j++)
    *(float4*)(bufq + (h + 2 * j) * 4) = hv[j];
}

__global__ __launch_bounds__(512) void psla_attn(const float* __restrict__ Ft,
                                                 float* __restrict__ out) {
  extern __shared__ float sm[];
  constexpr int kdx[NK] = {0, -1,-1,-1,0,0,1,1,1, -2,-2,-2,0,0,2,2,2,
                           -3,-3,-3,0,0,3,3,3, -4,-4,-4,0,0,4,4,4};
  constexpr int kdy[NK] = {0, -1,0,1,-1,1,-1,0,1, -2,0,2,-2,2,-2,0,2,
                           -3,0,3,-3,3,-3,0,3, -4,0,4,-4,4,-4,0,4};

  const int b = blockIdx.z;
  const int gx0 = blockIdx.x * 8, gy0 = blockIdx.y * 8;
  const int tid = threadIdx.x;
  const int px = tid >> 3, sub = tid & 7;
  const int lx = px & 7, ly = px >> 3;
  const int gx = gx0 + lx, gy = gy0 + ly;
  const int gp = gy * WW + gx;

  const float* Gb  = g_G + (size_t)b * CCH * HW;
  const float* Ftb = Ft + (size_t)b * CCH * HW;

  const int q = tid & 255;
  const int h = tid >> 8;  // 0 or 1
  const int hy = gy0 - 4 + (q >> 4);
  const int hx = gx0 - 4 + (q & 15);
  const bool hin = ((unsigned)hy < HH) && ((unsigned)hx < WW);
  const int haddr = hy * WW + hx;
  float* const myq0 = sm + q * SST;

  // Compute base: center site row + this sub's first channel group.
  const float* const cbase = sm + ((ly + 4) * 16 + (lx + 4)) * SST + sub * 4;

  unsigned long long vmask = 0ull;
#pragma unroll
  for (int k = 0; k < NK; k++)
    if ((unsigned)(gy + kdx[k]) < HH && (unsigned)(gx + kdy[k]) < WW)
      vmask |= (1ull << k);

  float aff[NK];
#pragma unroll
  for (int k = 0; k < NK; k++) aff[k] = 0.f;

  float4 hn[8];
  float eg[8], egn[8];

  // ==== Phase A: aff[k] = <G(p), Ft(p+delta_k)>, 4 chunks of 64 ch ====
  fetch64(Ftb, 0, h, hin, haddr, hn);
#pragma unroll
  for (int cc = 0; cc < 4; cc++) {
    eg[cc]     = Gb[(size_t)(sub * 4 + cc) * HW + gp];
    eg[4 + cc] = Gb[(size_t)(32 + sub * 4 + cc) * HW + gp];
  }
  store64(myq0, h, hn);
  __syncthreads();

  for (int c0 = 0; c0 < 4; c0++) {
    if (c0 < 3) {
      const int base = (c0 + 1) * 64;
      fetch64(Ftb, base, h, hin, haddr, hn);
#pragma unroll
      for (int cc = 0; cc < 4; cc++) {
        egn[cc]     = Gb[(size_t)(base + sub * 4 + cc) * HW + gp];
        egn[4 + cc] = Gb[(size_t)(base + 32 + sub * 4 + cc) * HW + gp];
      }
    }
    const float* bp = cbase + (c0 & 1) * ABUF;
#pragma unroll
    for (int k = 0; k < NK; k++) {
      const int off = (kdx[k] * 16 + kdy[k]) * SST;
      const float4 v0 = *(const float4*)(bp + off);
      const float4 v1 = *(const float4*)(bp + off + 32);
      float s = fmaf(eg[0], v0.x, 0.f);
      s = fmaf(eg[1], v0.y, s);
      s = fmaf(eg[2], v0.z, s);
      s = fmaf(eg[3], v0.w, s);
      s = fmaf(eg[4], v1.x, s);
      s = fmaf(eg[5], v1.y, s);
      s = fmaf(eg[6], v1.z, s);
      s = fmaf(eg[7], v1.w, s);
      aff[k] += s;
    }
    if (c0 < 3) {
      store64(myq0 + ((c0 & 1) ^ 1) * ABUF, h, hn);
#pragma unroll
      for (int cc = 0; cc < 8; cc++) eg[cc] = egn[cc];
    }
    __syncthreads();
  }

  // Reduce partial dots across the 8 channel-subgroups (lanes xor 1,2,4).
#pragma unroll
  for (int k = 0; k < NK; k++) {
    aff[k] += __shfl_xor_sync(0xffffffffu, aff[k], 1);
    aff[k] += __shfl_xor_sync(0xffffffffu, aff[k], 2);
    aff[k] += __shfl_xor_sync(0xffffffffu, aff[k], 4);
  }

  // ==== Softmax over valid offsets (k=0 always valid) ====
  float m = aff[0];
#pragma unroll
  for (int k = 1; k < NK; k++)
    if ((vmask >> k) & 1ull) m = fmaxf(m, aff[k]);
  float ssum = 0.f;
#pragma unroll
  for (int k = 0; k < NK; k++) {
    if ((vmask >> k) & 1ull) {
      aff[k] = __expf(aff[k] - m);
      ssum += aff[k];
    } else {
      aff[k] = 0.f;
    }
  }
  const float inv = 1.f / ssum;
#pragma unroll
  for (int k = 0; k < NK; k++) aff[k] *= inv;

  // ==== Phase B: out(c,p) = sum_k w_k * Ft(c,p+delta_k), FFMA2 ====
  fetch64(Ftb, 0, h, hin, haddr, hn);
  store64(myq0, h, hn);
  __syncthreads();

  for (int c0 = 0; c0 < 4; c0++) {
    if (c0 < 3) fetch64(Ftb, (c0 + 1) * 64, h, hin, haddr, hn);

    const float* bp = cbase + (c0 & 1) * ABUF;
    unsigned long long a01 = 0ull, a23 = 0ull, a45 = 0ull, a67 = 0ull;
#pragma unroll
    for (int k = 0; k < NK; k++) {
      const int off = (kdx[k] * 16 + kdy[k]) * SST;
      const ulonglong2 w0 = *(const ulonglong2*)(bp + off);
      const ulonglong2 w1 = *(const ulonglong2*)(bp + off + 32);
      const unsigned long long wk2 = pack2_bcast(aff[k]);
      a01 = ffma2(wk2, w0.x, a01);
      a23 = ffma2(wk2, w0.y, a23);
      a45 = ffma2(wk2, w1.x, a45);
      a67 = ffma2(wk2, w1.y, a67);
    }
    float o0, o1, o2, o3, o4, o5, o6, o7;
    unpack2(a01, o0, o1);
    unpack2(a23, o2, o3);
    unpack2(a45, o4, o5);
    unpack2(a67, o6, o7);
    float* op = out + (size_t)(b * CCH + c0 * 64 + sub * 4) * HW + gp;
    op[0] = o0;
    op[HW] = o1;
    op[2 * HW] = o2;
    op[3 * HW] = o3;
    op[32 * HW] = o4;
    op[33 * HW] = o5;
    op[34 * HW] = o6;
    op[35 * HW] = o7;

    if (c0 < 3) store64(myq0 + ((c0 & 1) ^ 1) * ABUF, h, hn);
    __syncthreads();
  }
}

// ---------------------------------------------------------------------------
extern "C" void kernel_launch(void* const* d_in, const int* in_sizes, int n_in,
                              void* d_out, int out_size) {
  const float* Ft  = (const float*)d_in[0];
  const float* Fte = (const float*)d_in[1];
  const float* Wf  = (const float*)d_in[2];
  // d_in[3] = bf: cancels in the softmax (constant in k) — unused.
  const float* Wg  = (const float*)d_in[4];
  const float* bg  = (const float*)d_in[5];
  float* out = (float*)d_out;

  cudaFuncSetAttribute(psla_gemm_fused,
                       cudaFuncAttributeMaxDynamicSharedMemorySize, FUSED_SMEM);
  const int attn_smem = 2 * ABUF * (int)sizeof(float);  // 139264 B
  cudaFuncSetAttribute(psla_attn, cudaFuncAttributeMaxDynamicSharedMemorySize,
                       attn_smem);

  psla_gemm_fused<<<128, 256, FUSED_SMEM>>>(Fte, Wf, Wg, bg);

  dim3 ga(8, 8, 2);  // W/8, H/8, B
  psla_attn<<<ga, 512, attn_smem>>>(Ft, out);
}